// round 12
// baseline (speedup 1.0000x reference)
#include <cuda_runtime.h>
#include <cuda_fp16.h>
#include <math.h>
#include <stdint.h>

#define TT 2048
#define HH 1024
#define FF 2816
#define NE 8
#define BM 128
#define GN 128      // gateup: N per operand (eff 256)
#define DBN 128     // down: N tile (round-10 proven config)
#define BKH 32
#define ASTR 40     // halves per smem row (32 + 8 pad) -> conflict-free ldmatrix

// ---------------- scratch ----------------
__device__ int    g_cnt[NE];
__device__ int    g_pref[NE + 1];   // prefix sum of per-expert m-block counts
__device__ int    g_tok[NE * TT];
__device__ float  g_wgt[NE * TT];
__device__ __half g_xh[(size_t)NE * TT * HH];
__device__ __half g_hh[(size_t)NE * TT * FF];

// ---------------- helpers ----------------
__device__ __forceinline__ uint32_t smem_u32(const void* p) {
    uint32_t a;
    asm("{ .reg .u64 t; cvta.to.shared.u64 t, %1; cvt.u32.u64 %0, t; }" : "=r"(a) : "l"(p));
    return a;
}
__device__ __forceinline__ void ldsm4(uint32_t* r, uint32_t a) {
    asm volatile("ldmatrix.sync.aligned.m8n8.x4.shared.b16 {%0,%1,%2,%3}, [%4];"
        : "=r"(r[0]), "=r"(r[1]), "=r"(r[2]), "=r"(r[3]) : "r"(a));
}
__device__ __forceinline__ void mma16816(float* d, const uint32_t* a, const uint32_t* b) {
    asm volatile("mma.sync.aligned.m16n8k16.row.col.f32.f16.f16.f32 "
        "{%0,%1,%2,%3}, {%4,%5,%6,%7}, {%8,%9}, {%0,%1,%2,%3};"
        : "+f"(d[0]), "+f"(d[1]), "+f"(d[2]), "+f"(d[3])
        : "r"(a[0]), "r"(a[1]), "r"(a[2]), "r"(a[3]), "r"(b[0]), "r"(b[1]));
}
__device__ __forceinline__ void cp16(uint32_t d, const void* s) {
    asm volatile("cp.async.ca.shared.global [%0], [%1], 16;" :: "r"(d), "l"(s));
}
#define CP_COMMIT() asm volatile("cp.async.commit_group;" ::: "memory")
#define CP_WAIT()   asm volatile("cp.async.wait_group 0;" ::: "memory")

__device__ __forceinline__ void sts8(__half* dst, float4 a, float4 b) {
    __half2 h0 = __floats2half2_rn(a.x, a.y);
    __half2 h1 = __floats2half2_rn(a.z, a.w);
    __half2 h2 = __floats2half2_rn(b.x, b.y);
    __half2 h3 = __floats2half2_rn(b.z, b.w);
    uint4 v;
    v.x = *(uint32_t*)&h0; v.y = *(uint32_t*)&h1;
    v.z = *(uint32_t*)&h2; v.w = *(uint32_t*)&h3;
    *(uint4*)dst = v;
}

// ---------------- setup kernels ----------------
__global__ void zero_kernel() {
    if (threadIdx.x < NE) g_cnt[threadIdx.x] = 0;
}

__global__ void router_kernel(const float* __restrict__ x, const float* __restrict__ Wgate) {
    int warp = (blockIdx.x * blockDim.x + threadIdx.x) >> 5;
    int lane = threadIdx.x & 31;
    if (warp >= TT) return;
    const float* xt = x + (size_t)warp * HH;
    float acc[NE];
#pragma unroll
    for (int e = 0; e < NE; e++) acc[e] = 0.f;
    for (int k = lane; k < HH; k += 32) {
        float xv = xt[k];
#pragma unroll
        for (int e = 0; e < NE; e++) acc[e] += xv * Wgate[e * HH + k];
    }
#pragma unroll
    for (int off = 16; off > 0; off >>= 1) {
#pragma unroll
        for (int e = 0; e < NE; e++) acc[e] += __shfl_xor_sync(0xffffffffu, acc[e], off);
    }
    if (lane == 0) {
        int i0 = 0; float l0 = acc[0];
#pragma unroll
        for (int e = 1; e < NE; e++) if (acc[e] > l0) { l0 = acc[e]; i0 = e; }
        int i1 = -1; float l1 = -INFINITY;
#pragma unroll
        for (int e = 0; e < NE; e++) if (e != i0 && acc[e] > l1) { l1 = acc[e]; i1 = e; }
        float w0 = 1.f / (1.f + __expf(l1 - l0));
        float w1 = 1.f - w0;
        int p0 = atomicAdd(&g_cnt[i0], 1);
        g_tok[i0 * TT + p0] = warp; g_wgt[i0 * TT + p0] = w0;
        int p1 = atomicAdd(&g_cnt[i1], 1);
        g_tok[i1 * TT + p1] = warp; g_wgt[i1 * TT + p1] = w1;
    }
}

// per-expert m-block counts -> prefix sums (tiny; one thread)
__global__ void prep_kernel() {
    if (threadIdx.x == 0) {
        int s = 0;
#pragma unroll
        for (int e = 0; e < NE; e++) {
            g_pref[e] = s;
            s += (g_cnt[e] + BM - 1) / BM;
        }
        g_pref[NE] = s;
    }
}

__global__ void gather_kernel(const float* __restrict__ x) {
    int slot = blockIdx.x * 8 + (threadIdx.x >> 5);
    int lane = threadIdx.x & 31;
    int e = slot / TT, r = slot % TT;
    if (r >= g_cnt[e]) return;
    int t = g_tok[e * TT + r];
    const float4* src = (const float4*)(x + (size_t)t * HH);
    __half2* dst = (__half2*)(g_xh + (size_t)slot * HH);
#pragma unroll
    for (int q = 0; q < HH / 128; q++) {
        float4 v = src[lane + q * 32];
        dst[(lane + q * 32) * 2 + 0] = __floats2half2_rn(v.x, v.y);
        dst[(lane + q * 32) * 2 + 1] = __floats2half2_rn(v.z, v.w);
    }
}

// ---------------- gate+up: persistent, BM=128 x GN=128/op, flat cross-tile pipeline ----------------
// 256 thr, warps 2x4, warp tile 64x32 per operand -> 128 accums. grid = 148 (1 CTA/SM).
// The kt-loop prefetch at the last k-step of a tile fetches stage 0 of the NEXT tile,
// so the smem pipeline never drains across tile boundaries.
__global__ __launch_bounds__(256) void gateup_hmma(const float* __restrict__ Wg,
                                                   const float* __restrict__ Wu) {
    const int STG = (BM + 2 * GN) * ASTR;  // halves per stage
    extern __shared__ __half sh[];

    int tid = threadIdx.x, lane = tid & 31, wid = tid >> 5;
    int wm = wid >> 2, wn = wid & 3;
    uint32_t sb = smem_u32(sh);

    int sumblk = g_pref[NE];
    int nact = (FF / GN) * sumblk;
    int i = blockIdx.x;
    if (i >= nact) return;

    // thread-invariant load mapping
    int ar[2], ac[2];
#pragma unroll
    for (int k = 0; k < 2; k++) { int ch = tid + k * 256; ar[k] = ch >> 2; ac[k] = ch & 3; }
    uint32_t adst[2];
#pragma unroll
    for (int k = 0; k < 2; k++) adst[k] = sb + (ar[k] * ASTR + ac[k] * 8) * 2;
    int br[4], bc[4]; __half* bstd[4];
#pragma unroll
    for (int k = 0; k < 4; k++) {
        int op = k >> 1;
        int idx = tid + (k & 1) * 256;
        br[k] = idx >> 2; bc[k] = idx & 3;
        bstd[k] = sh + (BM + op * GN) * ASTR + br[k] * ASTR + bc[k] * 8;
    }

    // fragment base addresses (stage 0)
    int seg = lane >> 3, li = lane & 7;
    uint32_t aA[4], aG[2], aU[2];
#pragma unroll
    for (int k = 0; k < 4; k++) {
        int row = wm * 64 + k * 16 + li + (seg & 1) * 8;
        aA[k] = sb + (row * ASTR + (seg >> 1) * 8) * 2;
    }
#pragma unroll
    for (int jj = 0; jj < 2; jj++) {
        int row = wn * 32 + jj * 16 + li + (seg >> 1) * 8;
        aG[jj] = sb + (BM * ASTR + row * ASTR + (seg & 1) * 8) * 2;
        aU[jj] = aG[jj] + GN * ASTR * 2;
    }

    // ---- decode tile i -> (e, n, m0, n0) + source pointers ----
    int e, n, m0, n0;
    const __half* asrc[2];
    const float*  bsrc[4];
    {
        int mslot = i % sumblk;
        int ee = 0;
#pragma unroll
        for (int q = 0; q < NE - 1; q++) if (mslot >= g_pref[q + 1]) ee = q + 1;
        e = ee; n = g_cnt[e];
        m0 = (mslot - g_pref[e]) * BM;
        n0 = (i / sumblk) * GN;
        const __half* xab = g_xh + (size_t)e * TT * HH;
#pragma unroll
        for (int k = 0; k < 2; k++) {
            int rc = m0 + ar[k]; if (rc >= n) rc = n - 1;
            asrc[k] = xab + (size_t)rc * HH + ac[k] * 8;
        }
        const float* wgb = Wg + (size_t)e * FF * HH;
        const float* wub = Wu + (size_t)e * FF * HH;
#pragma unroll
        for (int k = 0; k < 4; k++)
            bsrc[k] = ((k < 2) ? wgb : wub) + (size_t)(n0 + br[k]) * HH + bc[k] * 8;
    }

    float accg[4][4][4] = {}, accu[4][4][4] = {};
    float4 vb[4][2];

    // prologue: stage 0 of first tile
    cp16(adst[0], asrc[0]); cp16(adst[1], asrc[1]); CP_COMMIT();
#pragma unroll
    for (int k = 0; k < 4; k++) {
        vb[k][0] = *(const float4*)bsrc[k];
        vb[k][1] = *(const float4*)(bsrc[k] + 4);
    }
#pragma unroll
    for (int k = 0; k < 4; k++) sts8(bstd[k], vb[k][0], vb[k][1]);
    CP_WAIT();
    __syncthreads();

    int buf = 0;
    const int KT = HH / BKH;  // 32

    while (true) {
        int inext = i + gridDim.x;
        bool hasnext = (inext < nact);
        // saved for epilogue (asrc/bsrc get overwritten at kt==KT-1)
        int ce = e, cn = n, cm0 = m0, cn0 = n0;
        int ne_ = 0, nn_ = 0, nm0 = 0, nn0 = 0;

        for (int kt = 0; kt < KT; kt++) {
            uint32_t so = (uint32_t)(buf * STG * 2);
            bool pref = (kt + 1 < KT) || hasnext;
            int k0;
            if (kt + 1 < KT) {
                k0 = (kt + 1) * BKH;
            } else {
                k0 = 0;
                if (hasnext) {  // decode next tile, overwrite source pointers
                    int mslot = inext % sumblk;
                    int ee = 0;
#pragma unroll
                    for (int q = 0; q < NE - 1; q++) if (mslot >= g_pref[q + 1]) ee = q + 1;
                    ne_ = ee; nn_ = g_cnt[ee];
                    nm0 = (mslot - g_pref[ee]) * BM;
                    nn0 = (inext / sumblk) * GN;
                    const __half* xab = g_xh + (size_t)ne_ * TT * HH;
#pragma unroll
                    for (int k = 0; k < 2; k++) {
                        int rc = nm0 + ar[k]; if (rc >= nn_) rc = nn_ - 1;
                        asrc[k] = xab + (size_t)rc * HH + ac[k] * 8;
                    }
                    const float* wgb = Wg + (size_t)ne_ * FF * HH;
                    const float* wub = Wu + (size_t)ne_ * FF * HH;
#pragma unroll
                    for (int k = 0; k < 4; k++)
                        bsrc[k] = ((k < 2) ? wgb : wub) + (size_t)(nn0 + br[k]) * HH + bc[k] * 8;
                }
            }
            if (pref) {
                uint32_t po = (uint32_t)((buf ^ 1) * STG * 2);
                cp16(adst[0] + po, asrc[0] + k0);
                cp16(adst[1] + po, asrc[1] + k0);
                CP_COMMIT();
#pragma unroll
                for (int k = 0; k < 4; k++) {
                    vb[k][0] = *(const float4*)(bsrc[k] + k0);
                    vb[k][1] = *(const float4*)(bsrc[k] + k0 + 4);
                }
            }
#pragma unroll
            for (int ks = 0; ks < 2; ks++) {
                uint32_t af[4][4], bg[8], bu[8];
                ldsm4(&bg[0], aG[0] + so + ks * 32);
                ldsm4(&bg[4], aG[1] + so + ks * 32);
                ldsm4(&bu[0], aU[0] + so + ks * 32);
                ldsm4(&bu[4], aU[1] + so + ks * 32);
#pragma unroll
                for (int k = 0; k < 4; k++) ldsm4(af[k], aA[k] + so + ks * 32);
#pragma unroll
                for (int k = 0; k < 4; k++)
#pragma unroll
                    for (int j = 0; j < 4; j++) {
                        mma16816(accg[k][j], af[k], &bg[j * 2]);
                        mma16816(accu[k][j], af[k], &bu[j * 2]);
                    }
            }
            if (pref) {
                uint32_t po = (buf ^ 1) * STG;
#pragma unroll
                for (int k = 0; k < 4; k++) sts8(bstd[k] + po, vb[k][0], vb[k][1]);
                CP_WAIT();
            }
            __syncthreads();
            buf ^= 1;
        }

        // epilogue: SwiGLU -> fp16 g_hh (next tile's stage 0 already resident in smem)
#pragma unroll
        for (int k = 0; k < 4; k++) {
            int row0 = cm0 + wm * 64 + k * 16 + (lane >> 2);
            int row1 = row0 + 8;
#pragma unroll
            for (int j = 0; j < 4; j++) {
                int col = cn0 + wn * 32 + j * 8 + (lane & 3) * 2;
                if (row0 < cn) {
                    float a0 = accg[k][j][0], a1 = accg[k][j][1];
                    float h0 = (a0 / (1.f + __expf(-a0))) * accu[k][j][0];
                    float h1 = (a1 / (1.f + __expf(-a1))) * accu[k][j][1];
                    *(__half2*)(g_hh + ((size_t)ce * TT + row0) * FF + col) = __floats2half2_rn(h0, h1);
                }
                if (row1 < cn) {
                    float a2 = accg[k][j][2], a3 = accg[k][j][3];
                    float h2 = (a2 / (1.f + __expf(-a2))) * accu[k][j][2];
                    float h3 = (a3 / (1.f + __expf(-a3))) * accu[k][j][3];
                    *(__half2*)(g_hh + ((size_t)ce * TT + row1) * FF + col) = __floats2half2_rn(h2, h3);
                }
            }
        }

        if (!hasnext) break;
        // zero accumulators, advance
#pragma unroll
        for (int k = 0; k < 4; k++)
#pragma unroll
            for (int j = 0; j < 4; j++)
#pragma unroll
                for (int q = 0; q < 4; q++) { accg[k][j][q] = 0.f; accu[k][j][q] = 0.f; }
        i = inext; e = ne_; n = nn_; m0 = nm0; n0 = nn0;
    }
}

// ---------------- down: round-10 proven config (BM=128 x DBN=128, 2 CTA/SM, fused atomics) ----------------
__global__ __launch_bounds__(256, 2) void down_hmma(const float* __restrict__ Wd,
                                                    float* __restrict__ out) {
    const int STG = BM * ASTR + DBN * ASTR;
    __shared__ __half sh[2 * STG];

    int e = blockIdx.z, n = g_cnt[e];
    int m0 = blockIdx.x * BM;
    if (m0 >= n) return;
    int n0 = blockIdx.y * DBN;

    int tid = threadIdx.x, lane = tid & 31, wid = tid >> 5;
    int wm = wid >> 2, wn = wid & 3;
    uint32_t sb = smem_u32(sh);

    const __half* hab = g_hh + (size_t)e * TT * FF;
    const float*  wdb = Wd + (size_t)e * HH * FF;

    const __half* asrc[2]; uint32_t adst[2];
#pragma unroll
    for (int i = 0; i < 2; i++) {
        int ch = tid + i * 256, r = ch >> 2, c = ch & 3;
        int rc = m0 + r; if (rc >= n) rc = n - 1;
        asrc[i] = hab + (size_t)rc * FF + c * 8;
        adst[i] = sb + (r * ASTR + c * 8) * 2;
    }
    const float* bsrc[2]; __half* bst[2];
#pragma unroll
    for (int i = 0; i < 2; i++) {
        int task = tid + i * 256, r = task >> 2, c = task & 3;
        bsrc[i] = wdb + (size_t)(n0 + r) * FF + c * 8;
        bst[i] = sh + BM * ASTR + r * ASTR + c * 8;
    }

    int seg = lane >> 3, li = lane & 7;
    uint32_t aA[4], aB[2];
#pragma unroll
    for (int i = 0; i < 4; i++) {
        int row = wm * 64 + i * 16 + li + (seg & 1) * 8;
        aA[i] = sb + (row * ASTR + (seg >> 1) * 8) * 2;
    }
#pragma unroll
    for (int jj = 0; jj < 2; jj++) {
        int row = wn * 32 + jj * 16 + li + (seg >> 1) * 8;
        aB[jj] = sb + (BM * ASTR + row * ASTR + (seg & 1) * 8) * 2;
    }

    float acc[4][4][4] = {};

    cp16(adst[0], asrc[0]); cp16(adst[1], asrc[1]); CP_COMMIT();
    float4 vb[2][2];
#pragma unroll
    for (int i = 0; i < 2; i++) {
        vb[i][0] = *(const float4*)bsrc[i];
        vb[i][1] = *(const float4*)(bsrc[i] + 4);
    }
    sts8(bst[0], vb[0][0], vb[0][1]);
    sts8(bst[1], vb[1][0], vb[1][1]);
    CP_WAIT();
    __syncthreads();

    const int KT = FF / BKH;  // 88
    for (int kt = 0; kt < KT; kt++) {
        int cur = kt & 1;
        uint32_t so = (uint32_t)(cur * STG * 2);
        bool more = (kt + 1 < KT);
        if (more) {
            int k0 = (kt + 1) * BKH;
            uint32_t po = (uint32_t)((cur ^ 1) * STG * 2);
            cp16(adst[0] + po, asrc[0] + k0);
            cp16(adst[1] + po, asrc[1] + k0);
            CP_COMMIT();
#pragma unroll
            for (int i = 0; i < 2; i++) {
                vb[i][0] = *(const float4*)(bsrc[i] + k0);
                vb[i][1] = *(const float4*)(bsrc[i] + k0 + 4);
            }
        }
#pragma unroll
        for (int ks = 0; ks < 2; ks++) {
            uint32_t af[4][4], bf[8];
            ldsm4(&bf[0], aB[0] + so + ks * 32);
            ldsm4(&bf[4], aB[1] + so + ks * 32);
#pragma unroll
            for (int i = 0; i < 4; i++) ldsm4(af[i], aA[i] + so + ks * 32);
#pragma unroll
            for (int i = 0; i < 4; i++)
#pragma unroll
                for (int j = 0; j < 4; j++) mma16816(acc[i][j], af[i], &bf[j * 2]);
        }
        if (more) {
            __half* bo0 = bst[0] + (cur ^ 1) * STG;
            __half* bo1 = bst[1] + (cur ^ 1) * STG;
            sts8(bo0, vb[0][0], vb[0][1]);
            sts8(bo1, vb[1][0], vb[1][1]);
            CP_WAIT();
        }
        __syncthreads();
    }

#pragma unroll
    for (int i = 0; i < 4; i++) {
        int row0 = m0 + wm * 64 + i * 16 + (lane >> 2);
        int row1 = row0 + 8;
        bool v0 = row0 < n, v1 = row1 < n;
        int t0 = 0; float w0 = 0.f;
        if (v0) { t0 = g_tok[e * TT + row0]; w0 = g_wgt[e * TT + row0]; }
        int t1 = 0; float w1 = 0.f;
        if (v1) { t1 = g_tok[e * TT + row1]; w1 = g_wgt[e * TT + row1]; }
#pragma unroll
        for (int j = 0; j < 4; j++) {
            int col = n0 + wn * 32 + j * 8 + (lane & 3) * 2;
            if (v0) {
                float* p = out + (size_t)t0 * HH + col;
                atomicAdd(p + 0, acc[i][j][0] * w0);
                atomicAdd(p + 1, acc[i][j][1] * w0);
            }
            if (v1) {
                float* p = out + (size_t)t1 * HH + col;
                atomicAdd(p + 0, acc[i][j][2] * w1);
                atomicAdd(p + 1, acc[i][j][3] * w1);
            }
        }
    }
}

// ---------------- launch ----------------
extern "C" void kernel_launch(void* const* d_in, const int* in_sizes, int n_in,
                              void* d_out, int out_size) {
    const float* x     = (const float*)d_in[0];
    const float* Wgate = (const float*)d_in[1];
    const float* Wg    = (const float*)d_in[2];
    const float* Wu    = (const float*)d_in[3];
    const float* Wd    = (const float*)d_in[4];
    float* out = (float*)d_out;

    const int GU_SMEM = 2 * (BM + 2 * GN) * ASTR * 2;  // 61440 B
    cudaFuncSetAttribute(gateup_hmma, cudaFuncAttributeMaxDynamicSharedMemorySize, GU_SMEM);

    cudaMemsetAsync(out, 0, (size_t)TT * HH * sizeof(float));
    zero_kernel<<<1, 32>>>();
    router_kernel<<<TT / 8, 256>>>(x, Wgate);
    prep_kernel<<<1, 32>>>();
    gather_kernel<<<NE * TT / 8, 256>>>(x);
    gateup_hmma<<<148, 256, GU_SMEM>>>(Wg, Wu);
    down_hmma<<<dim3(TT / 128, HH / DBN, NE), 256>>>(Wd, out);
}

// round 13
// speedup vs baseline: 1.0922x; 1.0922x over previous
#include <cuda_runtime.h>
#include <cuda_fp16.h>
#include <math.h>
#include <stdint.h>

#define TT 2048
#define HH 1024
#define FF 2816
#define NE 8
#define BM 128
#define BN 64       // gateup N per operand
#define DBN 128     // down N tile
#define BKH 64      // k per pipeline stage (2x round-10: half the syncs)
#define ASTR 72     // halves per smem row (64 + 8 pad) -> conflict-free ldmatrix

// ---------------- scratch ----------------
__device__ int    g_cnt[NE];
__device__ int    g_tok[NE * TT];
__device__ float  g_wgt[NE * TT];
__device__ __half g_xh[(size_t)NE * TT * HH];
__device__ __half g_hh[(size_t)NE * TT * FF];

// ---------------- helpers ----------------
__device__ __forceinline__ uint32_t smem_u32(const void* p) {
    uint32_t a;
    asm("{ .reg .u64 t; cvta.to.shared.u64 t, %1; cvt.u32.u64 %0, t; }" : "=r"(a) : "l"(p));
    return a;
}
__device__ __forceinline__ void ldsm4(uint32_t* r, uint32_t a) {
    asm volatile("ldmatrix.sync.aligned.m8n8.x4.shared.b16 {%0,%1,%2,%3}, [%4];"
        : "=r"(r[0]), "=r"(r[1]), "=r"(r[2]), "=r"(r[3]) : "r"(a));
}
__device__ __forceinline__ void mma16816(float* d, const uint32_t* a, const uint32_t* b) {
    asm volatile("mma.sync.aligned.m16n8k16.row.col.f32.f16.f16.f32 "
        "{%0,%1,%2,%3}, {%4,%5,%6,%7}, {%8,%9}, {%0,%1,%2,%3};"
        : "+f"(d[0]), "+f"(d[1]), "+f"(d[2]), "+f"(d[3])
        : "r"(a[0]), "r"(a[1]), "r"(a[2]), "r"(a[3]), "r"(b[0]), "r"(b[1]));
}
__device__ __forceinline__ void cp16(uint32_t d, const void* s) {
    asm volatile("cp.async.ca.shared.global [%0], [%1], 16;" :: "r"(d), "l"(s));
}
#define CP_COMMIT() asm volatile("cp.async.commit_group;" ::: "memory")
#define CP_WAIT()   asm volatile("cp.async.wait_group 0;" ::: "memory")

__device__ __forceinline__ void sts8(__half* dst, float4 a, float4 b) {
    __half2 h0 = __floats2half2_rn(a.x, a.y);
    __half2 h1 = __floats2half2_rn(a.z, a.w);
    __half2 h2 = __floats2half2_rn(b.x, b.y);
    __half2 h3 = __floats2half2_rn(b.z, b.w);
    uint4 v;
    v.x = *(uint32_t*)&h0; v.y = *(uint32_t*)&h1;
    v.z = *(uint32_t*)&h2; v.w = *(uint32_t*)&h3;
    *(uint4*)dst = v;
}

// ---------------- setup kernels ----------------
__global__ void zero_kernel() {
    if (threadIdx.x < NE) g_cnt[threadIdx.x] = 0;
}

__global__ void router_kernel(const float* __restrict__ x, const float* __restrict__ Wgate) {
    int warp = (blockIdx.x * blockDim.x + threadIdx.x) >> 5;
    int lane = threadIdx.x & 31;
    if (warp >= TT) return;
    const float* xt = x + (size_t)warp * HH;
    float acc[NE];
#pragma unroll
    for (int e = 0; e < NE; e++) acc[e] = 0.f;
    for (int k = lane; k < HH; k += 32) {
        float xv = xt[k];
#pragma unroll
        for (int e = 0; e < NE; e++) acc[e] += xv * Wgate[e * HH + k];
    }
#pragma unroll
    for (int off = 16; off > 0; off >>= 1) {
#pragma unroll
        for (int e = 0; e < NE; e++) acc[e] += __shfl_xor_sync(0xffffffffu, acc[e], off);
    }
    if (lane == 0) {
        int i0 = 0; float l0 = acc[0];
#pragma unroll
        for (int e = 1; e < NE; e++) if (acc[e] > l0) { l0 = acc[e]; i0 = e; }
        int i1 = -1; float l1 = -INFINITY;
#pragma unroll
        for (int e = 0; e < NE; e++) if (e != i0 && acc[e] > l1) { l1 = acc[e]; i1 = e; }
        float w0 = 1.f / (1.f + expf(l1 - l0));
        float w1 = 1.f - w0;
        int p0 = atomicAdd(&g_cnt[i0], 1);
        g_tok[i0 * TT + p0] = warp; g_wgt[i0 * TT + p0] = w0;
        int p1 = atomicAdd(&g_cnt[i1], 1);
        g_tok[i1 * TT + p1] = warp; g_wgt[i1 * TT + p1] = w1;
    }
}

__global__ void gather_kernel(const float* __restrict__ x) {
    int slot = blockIdx.x * 8 + (threadIdx.x >> 5);
    int lane = threadIdx.x & 31;
    int e = slot / TT, r = slot % TT;
    if (r >= g_cnt[e]) return;
    int t = g_tok[e * TT + r];
    const float4* src = (const float4*)(x + (size_t)t * HH);
    __half2* dst = (__half2*)(g_xh + (size_t)slot * HH);
#pragma unroll
    for (int q = 0; q < HH / 128; q++) {
        float4 v = src[lane + q * 32];
        dst[(lane + q * 32) * 2 + 0] = __floats2half2_rn(v.x, v.y);
        dst[(lane + q * 32) * 2 + 1] = __floats2half2_rn(v.z, v.w);
    }
}

// ---------------- gate+up: 128x64(x2 ops), BKH=64, 2 CTA/SM, half-k staged weights ----------------
__global__ __launch_bounds__(256, 2) void gateup_hmma(const float* __restrict__ Wg,
                                                      const float* __restrict__ Wu) {
    const int STG = (BM + 2 * BN) * ASTR;  // halves per stage
    extern __shared__ __half sh[];

    int e = blockIdx.z, n = g_cnt[e];
    int m0 = blockIdx.x * BM;
    if (m0 >= n) return;
    int n0 = blockIdx.y * BN;

    int tid = threadIdx.x, lane = tid & 31, wid = tid >> 5;
    int wm = wid >> 2, wn = wid & 3;
    uint32_t sb = smem_u32(sh);

    const __half* xab = g_xh + (size_t)e * TT * HH;
    const float*  wgb = Wg + (size_t)e * FF * HH;
    const float*  wub = Wu + (size_t)e * FF * HH;

    // A cp.async: 128 rows x 8 chunks(16B) = 1024 chunks, 4/thread
    const __half* asrc[4]; uint32_t adst[4];
#pragma unroll
    for (int i = 0; i < 4; i++) {
        int ch = tid + i * 256, r = ch >> 3, c = ch & 7;
        int rc = m0 + r; if (rc >= n) rc = n - 1;
        asrc[i] = xab + (size_t)rc * HH + c * 8;
        adst[i] = sb + (r * ASTR + c * 8) * 2;
    }
    // B: per operand per half-k-set: 64 rows x 4 chunks(8 floats) -> 1 chunk/thread
    int brow = tid >> 2, bc = tid & 3;
    const float* gsrc = wgb + (size_t)(n0 + brow) * HH + bc * 8;
    const float* usrc = wub + (size_t)(n0 + brow) * HH + bc * 8;
    __half* bgst = sh + BM * ASTR + brow * ASTR + bc * 8;
    __half* bust = bgst + BN * ASTR;

    // fragment base addresses (stage 0)
    int seg = lane >> 3, li = lane & 7;
    uint32_t aA[4], aG, aU;
#pragma unroll
    for (int i = 0; i < 4; i++) {
        int row = wm * 64 + i * 16 + li + (seg & 1) * 8;
        aA[i] = sb + (row * ASTR + (seg >> 1) * 8) * 2;
    }
    {
        int row = wn * 16 + li + (seg >> 1) * 8;
        aG = sb + (BM * ASTR + row * ASTR + (seg & 1) * 8) * 2;
        aU = aG + BN * ASTR * 2;
    }

    float accg[4][2][4] = {}, accu[4][2][4] = {};
    float4 vg0, vg1, vu0, vu1;

    // prologue: stage 0 (both half-k sets)
#pragma unroll
    for (int i = 0; i < 4; i++) cp16(adst[i], asrc[i]);
    CP_COMMIT();
    vg0 = *(const float4*)gsrc; vg1 = *(const float4*)(gsrc + 4);
    vu0 = *(const float4*)usrc; vu1 = *(const float4*)(usrc + 4);
    sts8(bgst, vg0, vg1); sts8(bust, vu0, vu1);
    vg0 = *(const float4*)(gsrc + 32); vg1 = *(const float4*)(gsrc + 36);
    vu0 = *(const float4*)(usrc + 32); vu1 = *(const float4*)(usrc + 36);
    sts8(bgst + 32, vg0, vg1); sts8(bust + 32, vu0, vu1);
    CP_WAIT();
    __syncthreads();

    const int KT = HH / BKH;  // 16
    for (int kt = 0; kt < KT; kt++) {
        int cur = kt & 1;
        uint32_t so = (uint32_t)(cur * STG * 2);
        uint32_t po = (uint32_t)((cur ^ 1) * STG * 2);
        bool more = (kt + 1 < KT);
        int pk = (kt + 1) * BKH;
        if (more) {
#pragma unroll
            for (int i = 0; i < 4; i++) cp16(adst[i] + po, asrc[i] + pk);
            CP_COMMIT();
            vg0 = *(const float4*)(gsrc + pk); vg1 = *(const float4*)(gsrc + pk + 4);
            vu0 = *(const float4*)(usrc + pk); vu1 = *(const float4*)(usrc + pk + 4);
        }
#pragma unroll
        for (int ks = 0; ks < 2; ks++) {
            uint32_t af[4][4], bg[4], bu[4];
            ldsm4(bg, aG + so + ks * 32);
            ldsm4(bu, aU + so + ks * 32);
#pragma unroll
            for (int i = 0; i < 4; i++) ldsm4(af[i], aA[i] + so + ks * 32);
#pragma unroll
            for (int i = 0; i < 4; i++)
#pragma unroll
                for (int j = 0; j < 2; j++) {
                    mma16816(accg[i][j], af[i], &bg[j * 2]);
                    mma16816(accu[i][j], af[i], &bu[j * 2]);
                }
        }
        if (more) {
            __half* bo = bgst + (cur ^ 1) * STG;
            sts8(bo, vg0, vg1);
            sts8(bo + BN * ASTR, vu0, vu1);
            vg0 = *(const float4*)(gsrc + pk + 32); vg1 = *(const float4*)(gsrc + pk + 36);
            vu0 = *(const float4*)(usrc + pk + 32); vu1 = *(const float4*)(usrc + pk + 36);
        }
#pragma unroll
        for (int ks = 2; ks < 4; ks++) {
            uint32_t af[4][4], bg[4], bu[4];
            ldsm4(bg, aG + so + ks * 32);
            ldsm4(bu, aU + so + ks * 32);
#pragma unroll
            for (int i = 0; i < 4; i++) ldsm4(af[i], aA[i] + so + ks * 32);
#pragma unroll
            for (int i = 0; i < 4; i++)
#pragma unroll
                for (int j = 0; j < 2; j++) {
                    mma16816(accg[i][j], af[i], &bg[j * 2]);
                    mma16816(accu[i][j], af[i], &bu[j * 2]);
                }
        }
        if (more) {
            __half* bo = bgst + (cur ^ 1) * STG;
            sts8(bo + 32, vg0, vg1);
            sts8(bo + BN * ASTR + 32, vu0, vu1);
            CP_WAIT();
        }
        __syncthreads();
    }

    // epilogue: SwiGLU -> fp16 g_hh
#pragma unroll
    for (int i = 0; i < 4; i++) {
        int row0 = m0 + wm * 64 + i * 16 + (lane >> 2);
        int row1 = row0 + 8;
#pragma unroll
        for (int j = 0; j < 2; j++) {
            int col = n0 + wn * 16 + j * 8 + (lane & 3) * 2;
            if (row0 < n) {
                float a0 = accg[i][j][0], a1 = accg[i][j][1];
                float h0 = (a0 / (1.f + __expf(-a0))) * accu[i][j][0];
                float h1 = (a1 / (1.f + __expf(-a1))) * accu[i][j][1];
                *(__half2*)(g_hh + ((size_t)e * TT + row0) * FF + col) = __floats2half2_rn(h0, h1);
            }
            if (row1 < n) {
                float a2 = accg[i][j][2], a3 = accg[i][j][3];
                float h2 = (a2 / (1.f + __expf(-a2))) * accu[i][j][2];
                float h3 = (a3 / (1.f + __expf(-a3))) * accu[i][j][3];
                *(__half2*)(g_hh + ((size_t)e * TT + row1) * FF + col) = __floats2half2_rn(h2, h3);
            }
        }
    }
}

// ---------------- down: 128x128, BKH=64, 2 CTA/SM, fused atomic combine ----------------
__global__ __launch_bounds__(256, 2) void down_hmma(const float* __restrict__ Wd,
                                                    float* __restrict__ out) {
    const int STG = (BM + DBN) * ASTR;
    extern __shared__ __half sh[];

    int e = blockIdx.z, n = g_cnt[e];
    int m0 = blockIdx.x * BM;
    if (m0 >= n) return;
    int n0 = blockIdx.y * DBN;

    int tid = threadIdx.x, lane = tid & 31, wid = tid >> 5;
    int wm = wid >> 2, wn = wid & 3;
    uint32_t sb = smem_u32(sh);

    const __half* hab = g_hh + (size_t)e * TT * FF;
    const float*  wdb = Wd + (size_t)e * HH * FF;

    // A cp.async: 1024 chunks, 4/thread
    const __half* asrc[4]; uint32_t adst[4];
#pragma unroll
    for (int i = 0; i < 4; i++) {
        int ch = tid + i * 256, r = ch >> 3, c = ch & 7;
        int rc = m0 + r; if (rc >= n) rc = n - 1;
        asrc[i] = hab + (size_t)rc * FF + c * 8;
        adst[i] = sb + (r * ASTR + c * 8) * 2;
    }
    // B: per half-k-set 128 rows x 4 chunks = 512 tasks -> 2/thread
    const float* bsrc[2]; __half* bst[2];
#pragma unroll
    for (int i = 0; i < 2; i++) {
        int task = tid + i * 256, r = task >> 2, c = task & 3;
        bsrc[i] = wdb + (size_t)(n0 + r) * FF + c * 8;
        bst[i] = sh + BM * ASTR + r * ASTR + c * 8;
    }

    int seg = lane >> 3, li = lane & 7;
    uint32_t aA[4], aB[2];
#pragma unroll
    for (int i = 0; i < 4; i++) {
        int row = wm * 64 + i * 16 + li + (seg & 1) * 8;
        aA[i] = sb + (row * ASTR + (seg >> 1) * 8) * 2;
    }
#pragma unroll
    for (int jj = 0; jj < 2; jj++) {
        int row = wn * 32 + jj * 16 + li + (seg >> 1) * 8;
        aB[jj] = sb + (BM * ASTR + row * ASTR + (seg & 1) * 8) * 2;
    }

    float acc[4][4][4] = {};
    float4 vb[2][2];

    // prologue: stage 0 (both half-k sets)
#pragma unroll
    for (int i = 0; i < 4; i++) cp16(adst[i], asrc[i]);
    CP_COMMIT();
#pragma unroll
    for (int i = 0; i < 2; i++) {
        vb[i][0] = *(const float4*)bsrc[i];
        vb[i][1] = *(const float4*)(bsrc[i] + 4);
    }
    sts8(bst[0], vb[0][0], vb[0][1]);
    sts8(bst[1], vb[1][0], vb[1][1]);
#pragma unroll
    for (int i = 0; i < 2; i++) {
        vb[i][0] = *(const float4*)(bsrc[i] + 32);
        vb[i][1] = *(const float4*)(bsrc[i] + 36);
    }
    sts8(bst[0] + 32, vb[0][0], vb[0][1]);
    sts8(bst[1] + 32, vb[1][0], vb[1][1]);
    CP_WAIT();
    __syncthreads();

    const int KT = FF / BKH;  // 44
    for (int kt = 0; kt < KT; kt++) {
        int cur = kt & 1;
        uint32_t so = (uint32_t)(cur * STG * 2);
        uint32_t po = (uint32_t)((cur ^ 1) * STG * 2);
        bool more = (kt + 1 < KT);
        int pk = (kt + 1) * BKH;
        if (more) {
#pragma unroll
            for (int i = 0; i < 4; i++) cp16(adst[i] + po, asrc[i] + pk);
            CP_COMMIT();
#pragma unroll
            for (int i = 0; i < 2; i++) {
                vb[i][0] = *(const float4*)(bsrc[i] + pk);
                vb[i][1] = *(const float4*)(bsrc[i] + pk + 4);
            }
        }
#pragma unroll
        for (int ks = 0; ks < 2; ks++) {
            uint32_t af[4][4], bf[8];
            ldsm4(&bf[0], aB[0] + so + ks * 32);
            ldsm4(&bf[4], aB[1] + so + ks * 32);
#pragma unroll
            for (int i = 0; i < 4; i++) ldsm4(af[i], aA[i] + so + ks * 32);
#pragma unroll
            for (int i = 0; i < 4; i++)
#pragma unroll
                for (int j = 0; j < 4; j++) mma16816(acc[i][j], af[i], &bf[j * 2]);
        }
        if (more) {
            sts8(bst[0] + (cur ^ 1) * STG, vb[0][0], vb[0][1]);
            sts8(bst[1] + (cur ^ 1) * STG, vb[1][0], vb[1][1]);
#pragma unroll
            for (int i = 0; i < 2; i++) {
                vb[i][0] = *(const float4*)(bsrc[i] + pk + 32);
                vb[i][1] = *(const float4*)(bsrc[i] + pk + 36);
            }
        }
#pragma unroll
        for (int ks = 2; ks < 4; ks++) {
            uint32_t af[4][4], bf[8];
            ldsm4(&bf[0], aB[0] + so + ks * 32);
            ldsm4(&bf[4], aB[1] + so + ks * 32);
#pragma unroll
            for (int i = 0; i < 4; i++) ldsm4(af[i], aA[i] + so + ks * 32);
#pragma unroll
            for (int i = 0; i < 4; i++)
#pragma unroll
                for (int j = 0; j < 4; j++) mma16816(acc[i][j], af[i], &bf[j * 2]);
        }
        if (more) {
            sts8(bst[0] + (cur ^ 1) * STG + 32, vb[0][0], vb[0][1]);
            sts8(bst[1] + (cur ^ 1) * STG + 32, vb[1][0], vb[1][1]);
            CP_WAIT();
        }
        __syncthreads();
    }

    // epilogue: scale by combine weight, atomicAdd into out
#pragma unroll
    for (int i = 0; i < 4; i++) {
        int row0 = m0 + wm * 64 + i * 16 + (lane >> 2);
        int row1 = row0 + 8;
        bool v0 = row0 < n, v1 = row1 < n;
        int t0 = 0; float w0 = 0.f;
        if (v0) { t0 = g_tok[e * TT + row0]; w0 = g_wgt[e * TT + row0]; }
        int t1 = 0; float w1 = 0.f;
        if (v1) { t1 = g_tok[e * TT + row1]; w1 = g_wgt[e * TT + row1]; }
#pragma unroll
        for (int j = 0; j < 4; j++) {
            int col = n0 + wn * 32 + j * 8 + (lane & 3) * 2;
            if (v0) {
                float* p = out + (size_t)t0 * HH + col;
                atomicAdd(p + 0, acc[i][j][0] * w0);
                atomicAdd(p + 1, acc[i][j][1] * w0);
            }
            if (v1) {
                float* p = out + (size_t)t1 * HH + col;
                atomicAdd(p + 0, acc[i][j][2] * w1);
                atomicAdd(p + 1, acc[i][j][3] * w1);
            }
        }
    }
}

// ---------------- launch ----------------
extern "C" void kernel_launch(void* const* d_in, const int* in_sizes, int n_in,
                              void* d_out, int out_size) {
    const float* x     = (const float*)d_in[0];
    const float* Wgate = (const float*)d_in[1];
    const float* Wg    = (const float*)d_in[2];
    const float* Wu    = (const float*)d_in[3];
    const float* Wd    = (const float*)d_in[4];
    float* out = (float*)d_out;

    const int GU_SMEM = 2 * (BM + 2 * BN) * ASTR * 2;  // 73728 B
    const int DN_SMEM = 2 * (BM + DBN) * ASTR * 2;     // 73728 B
    cudaFuncSetAttribute(gateup_hmma, cudaFuncAttributeMaxDynamicSharedMemorySize, GU_SMEM);
    cudaFuncSetAttribute(down_hmma,   cudaFuncAttributeMaxDynamicSharedMemorySize, DN_SMEM);

    cudaMemsetAsync(out, 0, (size_t)TT * HH * sizeof(float));
    zero_kernel<<<1, 32>>>();
    router_kernel<<<TT / 8, 256>>>(x, Wgate);
    gather_kernel<<<NE * TT / 8, 256>>>(x);
    gateup_hmma<<<dim3(TT / 128, FF / BN, NE), 256, GU_SMEM>>>(Wg, Wu);
    down_hmma<<<dim3(TT / 128, HH / DBN, NE), 256, DN_SMEM>>>(Wd, out);
}